// round 15
// baseline (speedup 1.0000x reference)
#include <cuda_runtime.h>
#include <math.h>

#define BATCH 2
#define CDIM  512
#define HEADS 8
#define DHEAD 64
#define NPIX  4096
#define KTOP  32
#define GDIM  128

typedef unsigned long long ull;
typedef unsigned int uint32;

#define NEG_INF (__int_as_float(0xff800000))

// ---------------- scratch (device globals; no allocation allowed) ----------------
__device__ float g_q[BATCH*HEADS*DHEAD*NPIX];   // [b][h][d][n]
__device__ float g_k[BATCH*HEADS*DHEAD*NPIX];   // [b][h][d][n]
__device__ float g_v[BATCH*HEADS*NPIX*DHEAD];   // [b][h][n][d]
__device__ float g_g1[BATCH*NPIX*GDIM];         // [b][n][o]  gate hidden (bias applied)
__device__ float g_attn[BATCH*CDIM*NPIX];       // [b][c][n]  attention output (pre-proj)
__device__ int   g_kdyn[BATCH*NPIX];
__device__ float g_sim[(size_t)BATCH*HEADS*NPIX*NPIX];  // [bh][q][j]  1.07 GB

// ---------------- f32x2 helpers (sm_103a packed fp32) ----------------
__device__ __forceinline__ ull fma2(ull a, ull b, ull c) {
    ull d;
    asm("fma.rn.f32x2 %0, %1, %2, %3;" : "=l"(d) : "l"(a), "l"(b), "l"(c));
    return d;
}
__device__ __forceinline__ ull dup2(float x) {
    ull r; unsigned u = __float_as_uint(x);
    asm("mov.b64 %0, {%1, %1};" : "=l"(r) : "r"(u));
    return r;
}
__device__ __forceinline__ float lo2(ull x) { return __uint_as_float((unsigned)x); }
__device__ __forceinline__ float hi2(ull x) { return __uint_as_float((unsigned)(x >> 32)); }

// =====================================================================
// Kernel 1: fused qkv conv (1536 rows) + gate conv1 (128 rows) GEMM.
// (unchanged from passing R12 kernel)
// =====================================================================
__global__ void __launch_bounds__(128) k_qkv(const float* __restrict__ x,
                                             const float* __restrict__ w_qkv,
                                             const float* __restrict__ w_g1,
                                             const float* __restrict__ b_g1)
{
    __shared__ __align__(16) float As[32 * 68];
    __shared__ __align__(16) float Bs[32 * 64];
    const int b  = blockIdx.z;
    const int o0 = blockIdx.y * 64;
    const int n0 = blockIdx.x * 64;
    const int t  = threadIdx.x;
    const int to = (t >> 3) * 4;
    const int tn = (t & 7) * 2;          // interleaved: n = tn + p*16
    const float* xb = x + (size_t)b * CDIM * NPIX;

    ull acc[4][4];
#pragma unroll
    for (int i = 0; i < 4; i++)
#pragma unroll
        for (int p = 0; p < 4; p++) acc[i][p] = 0ULL;

    for (int c0 = 0; c0 < CDIM; c0 += 32) {
#pragma unroll
        for (int r = 0; r < 4; r++) {
            int e = t + r * 128;
            int o_l = e >> 3;
            int c_l = (e & 7) * 4;
            int o = o0 + o_l;
            const float* src = (o < 1536) ? (w_qkv + (size_t)o * CDIM + c0 + c_l)
                                          : (w_g1 + (size_t)(o - 1536) * CDIM + c0 + c_l);
            float4 v4 = *(const float4*)src;
            As[(c_l + 0) * 68 + o_l] = v4.x;
            As[(c_l + 1) * 68 + o_l] = v4.y;
            As[(c_l + 2) * 68 + o_l] = v4.z;
            As[(c_l + 3) * 68 + o_l] = v4.w;
        }
#pragma unroll
        for (int r = 0; r < 4; r++) {
            int e = t + r * 128;
            int c_l = e >> 4;
            int n_l = (e & 15) * 4;
            *(float4*)(Bs + c_l * 64 + n_l) =
                *(const float4*)(xb + (size_t)(c0 + c_l) * NPIX + n0 + n_l);
        }
        __syncthreads();
#pragma unroll
        for (int cc = 0; cc < 32; cc++) {
            ull a[4], bb[4];
#pragma unroll
            for (int i = 0; i < 4; i++) a[i] = dup2(As[cc * 68 + to + i]);
            const ull* bp = (const ull*)(Bs + cc * 64 + tn);
#pragma unroll
            for (int p = 0; p < 4; p++) bb[p] = bp[p * 8];
#pragma unroll
            for (int i = 0; i < 4; i++)
#pragma unroll
                for (int p = 0; p < 4; p++) acc[i][p] = fma2(a[i], bb[p], acc[i][p]);
        }
        __syncthreads();
    }

#pragma unroll
    for (int i = 0; i < 4; i++) {
        int o = o0 + to + i;
#pragma unroll
        for (int p = 0; p < 4; p++) {
            int n = n0 + tn + p * 16;
            float v0 = lo2(acc[i][p]);
            float v1 = hi2(acc[i][p]);
            if (o < 512) {
                int h = o >> 6, d = o & 63;
                float* dst = g_q + (((size_t)(b * HEADS + h)) * DHEAD + d) * NPIX + n;
                dst[0] = v0; dst[1] = v1;
            } else if (o < 1024) {
                int oo = o - 512; int h = oo >> 6, d = oo & 63;
                float* dst = g_k + (((size_t)(b * HEADS + h)) * DHEAD + d) * NPIX + n;
                dst[0] = v0; dst[1] = v1;
            } else if (o < 1536) {
                int oo = o - 1024; int h = oo >> 6, d = oo & 63;
                float* dst = g_v + (((size_t)(b * HEADS + h)) * NPIX + n) * DHEAD + d;
                dst[0] = v0; dst[DHEAD] = v1;
            } else {
                int oo = o - 1536;
                float bg = b_g1[oo];
                float* dst = g_g1 + ((size_t)b * NPIX + n) * GDIM + oo;
                dst[0] = v0 + bg; dst[GDIM] = v1 + bg;
            }
        }
    }
}

// =====================================================================
// Kernel 2: gate second conv -> sigmoid -> dynamic k. (unchanged)
// =====================================================================
__global__ void __launch_bounds__(128) k_gate(const float* __restrict__ w_g2,
                                              const float* __restrict__ b_g2)
{
    int p = blockIdx.x * 4 + (threadIdx.x >> 5);
    int lane = threadIdx.x & 31;
    const float* g = g_g1 + (size_t)p * GDIM;
    float acc = 0.f;
#pragma unroll
    for (int r = 0; r < 4; r++) {
        int o = lane + r * 32;
        float gv = g[o];
        gv = gv > 0.f ? gv : 0.f;
        acc += gv * w_g2[o];
    }
#pragma unroll
    for (int s = 16; s; s >>= 1) acc += __shfl_xor_sync(0xffffffffu, acc, s);
    if (lane == 0) {
        float tau = 1.f / (1.f + expf(-(acc + b_g2[0])));
        int kd = (int)(tau * 32.f);
        kd = kd < 4 ? 4 : (kd > 32 ? 32 : kd);
        g_kdyn[p] = kd;
    }
}

// =====================================================================
// Kernel 3a: sim GEMM -> global. 8q x 4j per thread:
//  - all lanes of a warp share the same 8 q-rows (tq = (t>>5)*8) ->
//    a-loads are float4 broadcasts from a TRANSPOSED q tile (1 wf each,
//    amortized over 4 dd => 2 wf/dd);
//  - each lane owns 4 consecutive j (tjc = (t&31)*4) -> one LDS.128
//    per dd (4 wf), conflict-free, and float4 coalesced global stores.
//  Per warp*dd: 6 wf vs 16 FFMA2 -> FMA-pipe bound.
//  dd-summation order per (q,j) unchanged -> bit-identical sim values.
// grid (NPIX/64 qtiles, B*HEADS), 256 threads, dynamic smem 50176 B.
// =====================================================================
#define SMEM_SIM 50176

__global__ void __launch_bounds__(256, 2) k_sim()
{
    extern __shared__ __align__(16) float sms[];
    float* qs_t = sms;            // [64 q][68 d]  (transposed, padded)
    float* ks   = sms + 4352;     // [64 d][128 j]

    const int bh = blockIdx.y;
    const int q0 = blockIdx.x * 64;
    const int t  = threadIdx.x;

    const float* qg = g_q + (size_t)bh * DHEAD * NPIX;
    const float* kg = g_k + (size_t)bh * DHEAD * NPIX;

    // load q tile transposed: coalesced global reads, strided smem writes
    for (int e = t; e < 4096; e += 256) {
        int q = e & 63, d = e >> 6;
        qs_t[q * 68 + d] = qg[(size_t)d * NPIX + q0 + q];
    }
    __syncthreads();

    const int tq  = (t >> 5) * 8;      // 8 q-rows per thread (warp-uniform)
    const int tjc = (t & 31) * 4;      // 4 consecutive j per thread

    for (int jt = 0; jt < 32; jt++) {
        for (int e = t; e < 2048; e += 256) {
            int d = e >> 5, j4 = (e & 31) * 4;
            *(float4*)(ks + d * 128 + j4) =
                *(const float4*)(kg + (size_t)d * NPIX + jt * 128 + j4);
        }
        __syncthreads();

        ull acc[8][2];
#pragma unroll
        for (int i = 0; i < 8; i++) { acc[i][0] = 0ULL; acc[i][1] = 0ULL; }

#pragma unroll 2
        for (int dd0 = 0; dd0 < 64; dd0 += 4) {
            float4 aq[8];
#pragma unroll
            for (int i = 0; i < 8; i++)
                aq[i] = *(const float4*)(qs_t + (tq + i) * 68 + dd0);
#pragma unroll
            for (int u = 0; u < 4; u++) {
                const ulonglong2 bv = *(const ulonglong2*)(ks + (dd0 + u) * 128 + tjc);
#pragma unroll
                for (int i = 0; i < 8; i++) {
                    const float* af = (const float*)&aq[i];
                    ull a = dup2(af[u]);
                    acc[i][0] = fma2(a, bv.x, acc[i][0]);
                    acc[i][1] = fma2(a, bv.y, acc[i][1]);
                }
            }
        }

#pragma unroll
        for (int i = 0; i < 8; i++) {
            float4 st;
            st.x = lo2(acc[i][0]) * 0.125f;
            st.y = hi2(acc[i][0]) * 0.125f;
            st.z = lo2(acc[i][1]) * 0.125f;
            st.w = hi2(acc[i][1]) * 0.125f;
            *(float4*)(g_sim + ((size_t)bh * NPIX + q0 + tq + i) * NPIX + jt * 128 + tjc) = st;
        }
        __syncthreads();
    }
}

// =====================================================================
// Kernel 3b: exact per-query top-32 (radix select) + kd-mask softmax +
//            weighted v gather. Level-0 histogram uses warp-aggregated
//            atomics (__match_any_sync) -- identical counts, ~8x fewer
//            ATOMS. Levels 1-3 keep plain atomics (few participants).
// =====================================================================
__global__ void __launch_bounds__(256) k_select()
{
    __shared__ uint32 hist[256];
    __shared__ uint32 svals[32];
    __shared__ int    sidx[32];
    __shared__ float  sortv[32];
    __shared__ int    sorti[32];
    __shared__ float  wsel[32];
    __shared__ int    kds[64];
    __shared__ float  outs[64 * 65];
    __shared__ uint32 bin_s, before_s;
    __shared__ int    cnt_s, gmin_s;

    const int bh = blockIdx.y;
    const int b  = bh >> 3;
    const int h  = bh & 7;
    const int q0 = blockIdx.x * 64;
    const int t  = threadIdx.x;
    const int lane = t & 31;

    const float* vg = g_v + (size_t)bh * NPIX * DHEAD;

    if (t < 64) kds[t] = g_kdyn[b * NPIX + q0 + t];
    __syncthreads();

    for (int q = 0; q < 64; q++) {
        const uint32* row = (const uint32*)g_sim + ((size_t)bh * NPIX + q0 + q) * NPIX;
        const int base = t * 16;
        uint32 vals[16];
#pragma unroll
        for (int u = 0; u < 4; u++) {
            uint4 w = *(const uint4*)(row + base + u * 4);
            vals[u * 4 + 0] = w.x; vals[u * 4 + 1] = w.y;
            vals[u * 4 + 2] = w.z; vals[u * 4 + 3] = w.w;
        }
#pragma unroll
        for (int i = 0; i < 16; i++) {
            uint32 u = vals[i];
            vals[i] = (u & 0x80000000u) ? ~u : (u | 0x80000000u);
        }

        uint32 prefix = 0;
        int remaining = 32;
#pragma unroll
        for (int lvl = 0; lvl < 4; lvl++) {
            const int sh = 24 - lvl * 8;
            const uint32 hiMask = (lvl == 0) ? 0u : (0xFFFFFFFFu << (32 - 8 * lvl));
            hist[t] = 0;
            __syncthreads();
            if (lvl == 0) {
                // warp-aggregated histogram: counts identical, few atomics
#pragma unroll
                for (int i = 0; i < 16; i++) {
                    uint32 bin = vals[i] >> 24;
                    unsigned mm = __match_any_sync(0xffffffffu, bin);
                    if (lane == (__ffs(mm) - 1)) atomicAdd(&hist[bin], (uint32)__popc(mm));
                }
            } else {
#pragma unroll
                for (int i = 0; i < 16; i++) {
                    uint32 v = vals[i];
                    if ((v & hiMask) == prefix) atomicAdd(&hist[(v >> sh) & 0xFF], 1u);
                }
            }
            __syncthreads();
            if (t < 32) {
                const int lo = 248 - t * 8;
                uint32 c[8]; uint32 csum = 0;
#pragma unroll
                for (int j = 0; j < 8; j++) { c[j] = hist[lo + j]; csum += c[j]; }
                uint32 inc = csum;
#pragma unroll
                for (int o = 1; o < 32; o <<= 1) {
                    uint32 x = __shfl_up_sync(0xffffffffu, inc, o);
                    if (t >= o) inc += x;
                }
                uint32 pre = inc - csum;
                if (pre < (uint32)remaining && inc >= (uint32)remaining) {
                    uint32 acc = pre; int sel = -1; uint32 before = 0;
#pragma unroll
                    for (int j = 7; j >= 0; j--) {
                        acc += c[j];
                        if (sel < 0 && acc >= (uint32)remaining) { sel = lo + j; before = acc - c[j]; }
                    }
                    bin_s = (uint32)sel; before_s = before;
                }
            }
            __syncthreads();
            prefix |= (bin_s << sh);
            remaining -= (int)before_s;
            __syncthreads();
        }
        const uint32 pivot = prefix;
        const int need = remaining;

        if (t == 0) cnt_s = 0;
        __syncthreads();
#pragma unroll
        for (int i = 0; i < 16; i++) {
            uint32 v = vals[i];
            if (v > pivot) { int p = atomicAdd(&cnt_s, 1); svals[p] = v; sidx[p] = base + i; }
        }
        __syncthreads();
        const int cg = cnt_s;

        int prevIdx = -1;
        for (int r = 0; r < need; r++) {
            if (t == 0) gmin_s = 0x7fffffff;
            __syncthreads();
            int best = 0x7fffffff;
#pragma unroll
            for (int i = 0; i < 16; i++) {
                if (vals[i] == pivot && (base + i) > prevIdx) { best = base + i; break; }
            }
            if (best != 0x7fffffff) atomicMin(&gmin_s, best);
            __syncthreads();
            int winner = gmin_s;
            if (t == 0) { svals[cg + r] = pivot; sidx[cg + r] = winner; }
            prevIdx = winner;
            __syncthreads();
        }

        if (t < 32) {
            uint32 vi = svals[t]; int ii = sidx[t];
            int rank = 0;
#pragma unroll
            for (int j = 0; j < 32; j++) {
                uint32 vj = svals[j]; int ij = sidx[j];
                rank += (vj > vi) || (vj == vi && ij < ii);
            }
            uint32 fb = (vi & 0x80000000u) ? (vi ^ 0x80000000u) : ~vi;
            sortv[rank] = __uint_as_float(fb);
            sorti[rank] = ii;
        }
        __syncthreads();

        if (t < 32) {
            int kd = kds[q];
            float m = sortv[0];
            float e = (t < kd) ? expf(sortv[t] - m) : 0.f;
            float s = e;
#pragma unroll
            for (int o = 16; o; o >>= 1) s += __shfl_xor_sync(0xffffffffu, s, o);
            wsel[t] = e / s;
        }
        __syncthreads();

        if (t < 64) {
            float acc = 0.f;
#pragma unroll 4
            for (int s = 0; s < 32; s++)
                acc += wsel[s] * vg[(size_t)sorti[s] * DHEAD + t];
            outs[t * 65 + q] = acc;
        }
        __syncthreads();
    }

    float* ab = g_attn + ((size_t)(b * CDIM + h * DHEAD)) * NPIX + q0;
    for (int e = t; e < 4096; e += 256) {
        int d = e >> 6, qq = e & 63;
        ab[(size_t)d * NPIX + qq] = outs[d * 65 + qq];
    }
}

// =====================================================================
// Kernel 4: proj conv + bias + residual. (unchanged from R12)
// =====================================================================
__global__ void __launch_bounds__(128) k_proj(const float* __restrict__ x,
                                              const float* __restrict__ w_proj,
                                              const float* __restrict__ b_proj,
                                              float* __restrict__ out)
{
    __shared__ __align__(16) float As[32 * 68];
    __shared__ __align__(16) float Bs[32 * 64];
    const int b  = blockIdx.z;
    const int o0 = blockIdx.y * 64;
    const int n0 = blockIdx.x * 64;
    const int t  = threadIdx.x;
    const int to = (t >> 3) * 4;
    const int tn = (t & 7) * 2;
    const float* ab = g_attn + (size_t)b * CDIM * NPIX;

    ull acc[4][4];
#pragma unroll
    for (int i = 0; i < 4; i++)
#pragma unroll
        for (int p = 0; p < 4; p++) acc[i][p] = 0ULL;

    for (int c0 = 0; c0 < CDIM; c0 += 32) {
#pragma unroll
        for (int r = 0; r < 4; r++) {
            int e = t + r * 128;
            int o_l = e >> 3;
            int c_l = (e & 7) * 4;
            float4 v4 = *(const float4*)(w_proj + (size_t)(o0 + o_l) * CDIM + c0 + c_l);
            As[(c_l + 0) * 68 + o_l] = v4.x;
            As[(c_l + 1) * 68 + o_l] = v4.y;
            As[(c_l + 2) * 68 + o_l] = v4.z;
            As[(c_l + 3) * 68 + o_l] = v4.w;
        }
#pragma unroll
        for (int r = 0; r < 4; r++) {
            int e = t + r * 128;
            int c_l = e >> 4;
            int n_l = (e & 15) * 4;
            *(float4*)(Bs + c_l * 64 + n_l) =
                *(const float4*)(ab + (size_t)(c0 + c_l) * NPIX + n0 + n_l);
        }
        __syncthreads();
#pragma unroll
        for (int cc = 0; cc < 32; cc++) {
            ull a[4], bb[4];
#pragma unroll
            for (int i = 0; i < 4; i++) a[i] = dup2(As[cc * 68 + to + i]);
            const ull* bp = (const ull*)(Bs + cc * 64 + tn);
#pragma unroll
            for (int p = 0; p < 4; p++) bb[p] = bp[p * 8];
#pragma unroll
            for (int i = 0; i < 4; i++)
#pragma unroll
                for (int p = 0; p < 4; p++) acc[i][p] = fma2(a[i], bb[p], acc[i][p]);
        }
        __syncthreads();
    }

#pragma unroll
    for (int i = 0; i < 4; i++) {
        int o = o0 + to + i;
        float bp0 = b_proj[o];
#pragma unroll
        for (int p = 0; p < 4; p++) {
            int n = n0 + tn + p * 16;
            size_t base = ((size_t)b * CDIM + o) * NPIX + n;
            out[base]     = lo2(acc[i][p]) + bp0 + x[base];
            out[base + 1] = hi2(acc[i][p]) + bp0 + x[base + 1];
        }
    }
}

// =====================================================================
extern "C" void kernel_launch(void* const* d_in, const int* in_sizes, int n_in,
                              void* d_out, int out_size)
{
    const float* x      = (const float*)d_in[0];
    const float* w_qkv  = (const float*)d_in[1];
    const float* w_proj = (const float*)d_in[2];
    const float* b_proj = (const float*)d_in[3];
    const float* w_g1   = (const float*)d_in[4];
    const float* b_g1   = (const float*)d_in[5];
    const float* w_g2   = (const float*)d_in[6];
    const float* b_g2   = (const float*)d_in[7];
    float* out = (float*)d_out;

    cudaFuncSetAttribute(k_sim, cudaFuncAttributeMaxDynamicSharedMemorySize, SMEM_SIM);

    k_qkv<<<dim3(NPIX / 64, 26, BATCH), 128>>>(x, w_qkv, w_g1, b_g1);
    k_gate<<<(BATCH * NPIX) / 4, 128>>>(w_g2, b_g2);
    k_sim<<<dim3(NPIX / 64, BATCH * HEADS), 256, SMEM_SIM>>>();
    k_select<<<dim3(NPIX / 64, BATCH * HEADS), 256>>>();
    k_proj<<<dim3(NPIX / 64, CDIM / 64, BATCH), 128>>>(x, w_proj, b_proj, out);
}